// round 14
// baseline (speedup 1.0000x reference)
#include <cuda_runtime.h>
#include <cuda_bf16.h>
#include <math.h>
#include <stdint.h>

// Problem constants
#define Bb     4
#define SEQ    2048
#define DIM    768
#define NH     12
#define DH     64
#define INNER  768
#define MROWS  (Bb * SEQ)   // 8192
#define NXF    (MROWS * DIM)      // 6291456 floats in x
#define NWF    (DIM * INNER)      // 589824 floats per weight

// Scratch (module-static device memory; allocation-free)
__device__ float g_x[NXF];                    // tf32-rounded x
__device__ float g_w[4 * NWF];                // tf32-rounded Wq,Wk,Wv,Wp
__device__ __align__(16) __nv_bfloat16 g_qb[Bb * NH * SEQ * DH];  // *log2e/8
__device__ __align__(16) __nv_bfloat16 g_kb[Bb * NH * SEQ * DH];  // [b][h][n][dh]
__device__ __align__(16) __nv_bfloat16 g_vt[Bb * NH * DH * SEQ];  // [b][h][dh][n]
__device__ float g_att[MROWS * INNER];        // attention out (tf32), [b*n][h*64+dh]

// ---------------------------------------------------------------------------
// Helpers
// ---------------------------------------------------------------------------
__device__ __forceinline__ float tf32r(float x) {
    uint32_t u;
    asm("cvt.rna.tf32.f32 %0, %1;" : "=r"(u) : "f"(x));
    return __uint_as_float(u);
}

__device__ __forceinline__ void mma_tf32(float d[4], const uint32_t a[4],
                                         const uint32_t b[2]) {
    asm volatile(
        "mma.sync.aligned.m16n8k8.row.col.f32.tf32.tf32.f32 "
        "{%0,%1,%2,%3}, {%4,%5,%6,%7}, {%8,%9}, {%0,%1,%2,%3};"
        : "+f"(d[0]), "+f"(d[1]), "+f"(d[2]), "+f"(d[3])
        : "r"(a[0]), "r"(a[1]), "r"(a[2]), "r"(a[3]), "r"(b[0]), "r"(b[1]));
}

__device__ __forceinline__ void mma_bf16(float d[4], const uint32_t a[4],
                                         const uint32_t b[2]) {
    asm volatile(
        "mma.sync.aligned.m16n8k16.row.col.f32.bf16.bf16.f32 "
        "{%0,%1,%2,%3}, {%4,%5,%6,%7}, {%8,%9}, {%0,%1,%2,%3};"
        : "+f"(d[0]), "+f"(d[1]), "+f"(d[2]), "+f"(d[3])
        : "r"(a[0]), "r"(a[1]), "r"(a[2]), "r"(a[3]), "r"(b[0]), "r"(b[1]));
}

// Warp-collective: load 4 8x8 b16 matrices.
__device__ __forceinline__ void ldmatrix_x4(uint32_t& r0, uint32_t& r1,
                                            uint32_t& r2, uint32_t& r3,
                                            uint32_t saddr) {
    asm volatile(
        "ldmatrix.sync.aligned.m8n8.x4.shared.b16 {%0,%1,%2,%3}, [%4];"
        : "=r"(r0), "=r"(r1), "=r"(r2), "=r"(r3) : "r"(saddr));
}

__device__ __forceinline__ uint32_t pack_bf16(float lo, float hi) {
    __nv_bfloat162 h = __floats2bfloat162_rn(lo, hi);
    return *(uint32_t*)&h;
}

__device__ __forceinline__ void cp16(uint32_t saddr, const void* gaddr) {
    asm volatile("cp.async.cg.shared.global [%0], [%1], 16;" :: "r"(saddr), "l"(gaddr));
}
#define CP_COMMIT()  asm volatile("cp.async.commit_group;")
#define CP_WAIT1()   asm volatile("cp.async.wait_group 1;" ::: "memory")
#define CP_WAIT0()   asm volatile("cp.async.wait_group 0;" ::: "memory")

// ---------------------------------------------------------------------------
// Kernel 0: round x and the 4 weight matrices to tf32 (elementwise, once).
// ---------------------------------------------------------------------------
__global__ void round_kernel(const float* __restrict__ x,
                             const float* __restrict__ Wq,
                             const float* __restrict__ Wk,
                             const float* __restrict__ Wv,
                             const float* __restrict__ Wp) {
    const int base = (blockIdx.x * 256 + threadIdx.x) * 4;
    if (base < NXF) {
        float4 v = *(const float4*)&x[base];
        v.x = tf32r(v.x); v.y = tf32r(v.y); v.z = tf32r(v.z); v.w = tf32r(v.w);
        *(float4*)&g_x[base] = v;
    } else {
        const int j = base - NXF;
        const int w = j / NWF;
        const int off = j - w * NWF;
        const float* src = (w == 0) ? Wq : (w == 1) ? Wk : (w == 2) ? Wv : Wp;
        float4 v = *(const float4*)&src[off];
        v.x = tf32r(v.x); v.y = tf32r(v.y); v.z = tf32r(v.z); v.w = tf32r(v.w);
        *(float4*)&g_w[w * NWF + off] = v;
    }
}

// ---------------------------------------------------------------------------
// QKV GEMM smem geometry: BM=128, BN=128, BK=32, 3-stage cp.async.
// ---------------------------------------------------------------------------
#define ASTRIDE   36
#define BSTRIDE   136
#define AS_STAGE  (128 * ASTRIDE)          // 4608 floats
#define BS_BASE   (3 * AS_STAGE)           // 13824
#define BS_STAGE  (32 * BSTRIDE)           // 4352
#define GEMM_SMEM_FLOATS (BS_BASE + 3 * BS_STAGE)   // 26880 -> 107520 B

__device__ __forceinline__ void gemm_fill(uint32_t su, int st, int k0,
                                          const float* __restrict__ gA, int bm,
                                          const float* __restrict__ gB, int bn,
                                          int t) {
#pragma unroll
    for (int i = 0; i < 4; i++) {
        const int lin = t + i * 256;
        const int row = lin >> 3;
        const int col = (lin & 7) * 4;
        cp16(su + (uint32_t)(st * AS_STAGE + row * ASTRIDE + col) * 4,
             &gA[(size_t)(bm + row) * DIM + k0 + col]);
    }
#pragma unroll
    for (int i = 0; i < 4; i++) {
        const int lin = t + i * 256;
        const int row = lin >> 5;
        const int col = (lin & 31) * 4;
        cp16(su + (uint32_t)(BS_BASE + st * BS_STAGE + row * BSTRIDE + col) * 4,
             &gB[(size_t)(k0 + row) * INNER + bn + col]);
    }
}

__device__ __forceinline__ void gemm_compute(const float* __restrict__ smf, int st,
                                             int m_base, int n_base, int qr, int qc,
                                             float acc[2][8][4]) {
    const uint32_t* A = (const uint32_t*)(smf + st * AS_STAGE);
    const uint32_t* Bm = (const uint32_t*)(smf + BS_BASE + st * BS_STAGE);
#pragma unroll
    for (int ks = 0; ks < 4; ks++) {
        const int kk = ks * 8;
        uint32_t a[2][4];
#pragma unroll
        for (int mt = 0; mt < 2; mt++) {
            const int row = m_base + mt * 16 + qr;
            a[mt][0] = A[row * ASTRIDE + kk + qc];
            a[mt][1] = A[(row + 8) * ASTRIDE + kk + qc];
            a[mt][2] = A[row * ASTRIDE + kk + 4 + qc];
            a[mt][3] = A[(row + 8) * ASTRIDE + kk + 4 + qc];
        }
#pragma unroll
        for (int j = 0; j < 8; j++) {
            uint32_t b[2];
            const int col = n_base + j * 8 + qr;
            b[0] = Bm[(kk + qc) * BSTRIDE + col];
            b[1] = Bm[(kk + 4 + qc) * BSTRIDE + col];
#pragma unroll
            for (int mt = 0; mt < 2; mt++) mma_tf32(acc[mt][j], a[mt], b);
        }
    }
}

// ---------------------------------------------------------------------------
// Kernel 1: persistent fused QKV projection (tf32 MMA), bf16 outputs.
// ---------------------------------------------------------------------------
#define QSCALE 0.1803368801111204f   // 0.125 * log2(e)
#define QKV_UNITS (3 * 64 * 6)       // 1152

__global__ __launch_bounds__(256, 2) void qkv_kernel() {
    extern __shared__ float smf[];
    const uint32_t su = (uint32_t)__cvta_generic_to_shared(smf);

    const int t  = threadIdx.x;
    const int warp = t >> 5;
    const int lane = t & 31;
    const int m_base = (warp >> 1) * 32;
    const int n_base = (warp & 1) * 64;
    const int qr = lane >> 2;
    const int qc = lane & 3;

    for (int unit = blockIdx.x; unit < QKV_UNITS; unit += gridDim.x) {
        __syncthreads();

        const int z      = unit / 384;
        const int rem    = unit - z * 384;
        const int bm     = (rem / 6) * 128;
        const int bn     = (rem % 6) * 128;

        const float* W;
        __nv_bfloat16* outp;
        float scale = 1.0f;
        bool transpose = false;
        if (z == 0)      { W = g_w;           outp = g_qb; scale = QSCALE; }
        else if (z == 1) { W = g_w + NWF;     outp = g_kb; }
        else             { W = g_w + 2 * NWF; outp = g_vt; transpose = true; }

        float acc[2][8][4];
#pragma unroll
        for (int mt = 0; mt < 2; mt++)
#pragma unroll
            for (int j = 0; j < 8; j++)
#pragma unroll
                for (int e = 0; e < 4; e++) acc[mt][j][e] = 0.0f;

        gemm_fill(su, 0, 0, g_x, bm, W, bn, t);
        CP_COMMIT();
        gemm_fill(su, 1, 32, g_x, bm, W, bn, t);
        CP_COMMIT();

        int cs = 0, fs = 2;
        for (int kt = 0; kt < DIM / 32; kt++) {
            if (kt + 1 < DIM / 32) { CP_WAIT1(); } else { CP_WAIT0(); }
            __syncthreads();
            if (kt + 2 < DIM / 32) {
                gemm_fill(su, fs, (kt + 2) * 32, g_x, bm, W, bn, t);
                CP_COMMIT();
            }
            gemm_compute(smf, cs, m_base, n_base, qr, qc, acc);
            cs = (cs == 2) ? 0 : cs + 1;
            fs = (fs == 2) ? 0 : fs + 1;
        }

#pragma unroll
        for (int mt = 0; mt < 2; mt++) {
#pragma unroll
            for (int j = 0; j < 8; j++) {
#pragma unroll
                for (int e = 0; e < 4; e++) {
                    const int row = bm + m_base + mt * 16 + qr + (e >= 2 ? 8 : 0);
                    const int col = bn + n_base + j * 8 + 2 * qc + (e & 1);
                    const int bidx = row >> 11;
                    const int n    = row & 2047;
                    const int h    = col >> 6;
                    const int dh   = col & 63;
                    const size_t idx = transpose
                        ? ((((size_t)bidx * NH + h) * DH) + dh) * SEQ + n
                        : ((((size_t)bidx * NH + h) * SEQ) + n) * DH + dh;
                    outp[idx] = __float2bfloat16(acc[mt][j][e] * scale);
                }
            }
        }
    }
}

// ---------------------------------------------------------------------------
// Kernel 2: persistent flash attention (unchanged from round 12)
// ---------------------------------------------------------------------------
#define UKSTRIDE   36
#define KV_STAGE_U (64 * UKSTRIDE)                 // 2304
#define VS_BASE_U  (3 * KV_STAGE_U)                // 6912
#define PS_BASE_U  (VS_BASE_U + 3 * KV_STAGE_U)    // 13824
#define FLASH_SMEM_U (PS_BASE_U + 128 * UKSTRIDE)  // 18432 -> 73728 B
#define FLASH_UNITS (Bb * NH * (SEQ / 128))        // 768

__global__ __launch_bounds__(256, 2) void flash_kernel() {
    extern __shared__ uint32_t smu[];
    const uint32_t su = (uint32_t)__cvta_generic_to_shared(smu);
    uint32_t* Psu = smu + PS_BASE_U;

    const int t  = threadIdx.x;
    const int warp = t >> 5;
    const int lane = t & 31;
    const int qr = lane >> 2;
    const int qc = lane & 3;
    const int wrow = warp * 16;

    const int lm_row = (lane & 7) + ((lane & 16) >> 1);
    const int lm_col = (lane & 8) >> 1;
    const uint32_t lm_off = (uint32_t)(lm_row * UKSTRIDE + lm_col) * 4;

    for (int unit = blockIdx.x; unit < FLASH_UNITS; unit += gridDim.x) {
        __syncthreads();

        const int qt = unit & 15;
        const int bh = unit >> 4;
        const int h  = bh % NH;
        const int b  = bh / NH;

        const size_t head_nd = ((size_t)b * NH + h) * SEQ * DH;
        const __nv_bfloat16* qbase  = g_qb + head_nd + (size_t)qt * 128 * DH;
        const __nv_bfloat16* kbase  = g_kb + head_nd;
        const __nv_bfloat16* vtbase = g_vt + head_nd;

#pragma unroll
        for (int st = 0; st < 2; st++) {
            const __nv_bfloat16* ktile = kbase + (size_t)st * 64 * DH;
            const __nv_bfloat16* vtile = vtbase + (size_t)st * 64;
#pragma unroll
            for (int i = 0; i < 2; i++) {
                const int lin = t + i * 256;
                const int row = lin >> 3;
                const int ch  = lin & 7;
                cp16(su + (uint32_t)(st * KV_STAGE_U + row * UKSTRIDE + ch * 4) * 4,
                     ktile + row * DH + ch * 8);
                cp16(su + (uint32_t)(VS_BASE_U + st * KV_STAGE_U + row * UKSTRIDE + ch * 4) * 4,
                     vtile + (size_t)row * SEQ + ch * 8);
            }
            CP_COMMIT();
        }

#pragma unroll
        for (int i = 0; i < 4; i++) {
            const int lin = t + i * 256;
            const int row = lin >> 3;
            const int ch  = lin & 7;
            *(float4*)&Psu[row * UKSTRIDE + ch * 4] =
                *(const float4*)&qbase[row * DH + ch * 8];
        }
        __syncthreads();

        uint32_t qf[4][4];
#pragma unroll
        for (int ks = 0; ks < 4; ks++) {
            qf[ks][0] = Psu[(wrow + qr) * UKSTRIDE + ks * 8 + qc];
            qf[ks][1] = Psu[(wrow + qr + 8) * UKSTRIDE + ks * 8 + qc];
            qf[ks][2] = Psu[(wrow + qr) * UKSTRIDE + ks * 8 + 4 + qc];
            qf[ks][3] = Psu[(wrow + qr + 8) * UKSTRIDE + ks * 8 + 4 + qc];
        }

        float o[8][4];
#pragma unroll
        for (int j = 0; j < 8; j++)
#pragma unroll
            for (int e = 0; e < 4; e++) o[j][e] = 0.0f;
        float m_lo = -INFINITY, m_hi = -INFINITY, l_lo = 0.0f, l_hi = 0.0f;

        int cs = 0, fs = 2;
        for (int kt = 0; kt < SEQ / 64; kt++) {
            if (kt + 1 < SEQ / 64) { CP_WAIT1(); } else { CP_WAIT0(); }
            __syncthreads();
            if (kt + 2 < SEQ / 64) {
                const __nv_bfloat16* ktile = kbase + (size_t)(kt + 2) * 64 * DH;
                const __nv_bfloat16* vtile = vtbase + (size_t)(kt + 2) * 64;
#pragma unroll
                for (int i = 0; i < 2; i++) {
                    const int lin = t + i * 256;
                    const int row = lin >> 3;
                    const int ch  = lin & 7;
                    cp16(su + (uint32_t)(fs * KV_STAGE_U + row * UKSTRIDE + ch * 4) * 4,
                         ktile + row * DH + ch * 8);
                    cp16(su + (uint32_t)(VS_BASE_U + fs * KV_STAGE_U + row * UKSTRIDE + ch * 4) * 4,
                         vtile + (size_t)row * SEQ + ch * 8);
                }
                CP_COMMIT();
            }

            const uint32_t k_lm = su + (uint32_t)(cs * KV_STAGE_U) * 4 + lm_off;
            const uint32_t v_lm = su + (uint32_t)(VS_BASE_U + cs * KV_STAGE_U) * 4 + lm_off;

            float s[8][4];
#pragma unroll
            for (int j = 0; j < 8; j++)
#pragma unroll
                for (int e = 0; e < 4; e++) s[j][e] = 0.0f;
#pragma unroll
            for (int ks = 0; ks < 4; ks++) {
#pragma unroll
                for (int jp = 0; jp < 4; jp++) {
                    uint32_t b0, b1, b2, b3;
                    ldmatrix_x4(b0, b1, b2, b3,
                                k_lm + (uint32_t)(jp * 16 * UKSTRIDE + ks * 8) * 4);
                    uint32_t br0[2] = {b0, b1};
                    uint32_t br1[2] = {b2, b3};
                    mma_bf16(s[2 * jp],     qf[ks], br0);
                    mma_bf16(s[2 * jp + 1], qf[ks], br1);
                }
            }

            float mx_lo = m_lo, mx_hi = m_hi;
#pragma unroll
            for (int j = 0; j < 8; j++) {
                mx_lo = fmaxf(mx_lo, fmaxf(s[j][0], s[j][1]));
                mx_hi = fmaxf(mx_hi, fmaxf(s[j][2], s[j][3]));
            }
            mx_lo = fmaxf(mx_lo, __shfl_xor_sync(0xffffffffu, mx_lo, 1));
            mx_lo = fmaxf(mx_lo, __shfl_xor_sync(0xffffffffu, mx_lo, 2));
            mx_hi = fmaxf(mx_hi, __shfl_xor_sync(0xffffffffu, mx_hi, 1));
            mx_hi = fmaxf(mx_hi, __shfl_xor_sync(0xffffffffu, mx_hi, 2));

            const float c_lo = exp2f(m_lo - mx_lo);
            const float c_hi = exp2f(m_hi - mx_hi);
            float sum_lo = 0.0f, sum_hi = 0.0f;
#pragma unroll
            for (int j = 0; j < 8; j++) {
                s[j][0] = exp2f(s[j][0] - mx_lo);
                s[j][1] = exp2f(s[j][1] - mx_lo);
                s[j][2] = exp2f(s[j][2] - mx_hi);
                s[j][3] = exp2f(s[j][3] - mx_hi);
                sum_lo += s[j][0] + s[j][1];
                sum_hi += s[j][2] + s[j][3];
            }
            sum_lo += __shfl_xor_sync(0xffffffffu, sum_lo, 1);
            sum_lo += __shfl_xor_sync(0xffffffffu, sum_lo, 2);
            sum_hi += __shfl_xor_sync(0xffffffffu, sum_hi, 1);
            sum_hi += __shfl_xor_sync(0xffffffffu, sum_hi, 2);
            l_lo = l_lo * c_lo + sum_lo;
            l_hi = l_hi * c_hi + sum_hi;
            m_lo = mx_lo;
            m_hi = mx_hi;

#pragma unroll
            for (int j = 0; j < 8; j++) {
                o[j][0] *= c_lo; o[j][1] *= c_lo;
                o[j][2] *= c_hi; o[j][3] *= c_hi;
            }

#pragma unroll
            for (int ks = 0; ks < 4; ks++) {
                uint32_t a[4];
                a[0] = pack_bf16(s[2 * ks][0],     s[2 * ks][1]);
                a[1] = pack_bf16(s[2 * ks][2],     s[2 * ks][3]);
                a[2] = pack_bf16(s[2 * ks + 1][0], s[2 * ks + 1][1]);
                a[3] = pack_bf16(s[2 * ks + 1][2], s[2 * ks + 1][3]);
#pragma unroll
                for (int jp = 0; jp < 4; jp++) {
                    uint32_t b0, b1, b2, b3;
                    ldmatrix_x4(b0, b1, b2, b3,
                                v_lm + (uint32_t)(jp * 16 * UKSTRIDE + ks * 8) * 4);
                    uint32_t br0[2] = {b0, b1};
                    uint32_t br1[2] = {b2, b3};
                    mma_bf16(o[2 * jp],     a, br0);
                    mma_bf16(o[2 * jp + 1], a, br1);
                }
            }

            cs = (cs == 2) ? 0 : cs + 1;
            fs = (fs == 2) ? 0 : fs + 1;
        }

        const float inv_lo = 1.0f / l_lo;
        const float inv_hi = 1.0f / l_hi;
        const int n_lo = qt * 128 + wrow + qr;
#pragma unroll
        for (int j = 0; j < 8; j++) {
            const int col = h * 64 + j * 8 + 2 * qc;
            *(float2*)&g_att[((size_t)b * SEQ + n_lo) * INNER + col] =
                make_float2(tf32r(o[j][0] * inv_lo), tf32r(o[j][1] * inv_lo));
            *(float2*)&g_att[((size_t)b * SEQ + n_lo + 8) * INNER + col] =
                make_float2(tf32r(o[j][2] * inv_hi), tf32r(o[j][3] * inv_hi));
        }
    }
}

// ---------------------------------------------------------------------------
// Kernel 3: output projection, BM=128 x BN=64 tiles (768 CTAs -> fine-grained
// waves), tf32 MMA, 3-stage cp.async. Warp tile 32x32; acc[2][4][4].
// ---------------------------------------------------------------------------
#define PJ_BSTRIDE   72
#define PJ_BS_BASE   (3 * AS_STAGE)          // reuse A geometry: 13824
#define PJ_BS_STAGE  (32 * PJ_BSTRIDE)       // 2304
#define PJ_SMEM_FLOATS (PJ_BS_BASE + 3 * PJ_BS_STAGE)   // 20736 -> 82944 B

__global__ __launch_bounds__(256, 2) void proj_kernel(const float* __restrict__ bp,
                                                      float* __restrict__ out) {
    extern __shared__ float smf[];
    const uint32_t su = (uint32_t)__cvta_generic_to_shared(smf);
    const float* Wp = g_w + 3 * (size_t)NWF;

    const int bm = blockIdx.y * 128;
    const int bn = blockIdx.x * 64;
    const int t  = threadIdx.x;
    const int warp = t >> 5;
    const int lane = t & 31;
    const int m_base = (warp >> 1) * 32;
    const int n_base = (warp & 1) * 32;
    const int qr = lane >> 2;
    const int qc = lane & 3;

    float acc[2][4][4];
#pragma unroll
    for (int mt = 0; mt < 2; mt++)
#pragma unroll
        for (int j = 0; j < 4; j++)
#pragma unroll
            for (int e = 0; e < 4; e++) acc[mt][j][e] = 0.0f;

    // fill helper inline (A: 128x32 as gemm_fill; B: 32x64)
    auto pj_fill = [&](int st, int k0) {
#pragma unroll
        for (int i = 0; i < 4; i++) {
            const int lin = t + i * 256;
            const int row = lin >> 3;
            const int col = (lin & 7) * 4;
            cp16(su + (uint32_t)(st * AS_STAGE + row * ASTRIDE + col) * 4,
                 &g_att[(size_t)(bm + row) * INNER + k0 + col]);
        }
#pragma unroll
        for (int i = 0; i < 2; i++) {
            const int lin = t + i * 256;
            const int row = lin >> 4;           // 0..31
            const int col = (lin & 15) * 4;     // 0..60
            cp16(su + (uint32_t)(PJ_BS_BASE + st * PJ_BS_STAGE + row * PJ_BSTRIDE + col) * 4,
                 &Wp[(size_t)(k0 + row) * DIM + bn + col]);
        }
    };

    pj_fill(0, 0);
    CP_COMMIT();
    pj_fill(1, 32);
    CP_COMMIT();

    int cs = 0, fs = 2;
    for (int kt = 0; kt < INNER / 32; kt++) {
        if (kt + 1 < INNER / 32) { CP_WAIT1(); } else { CP_WAIT0(); }
        __syncthreads();
        if (kt + 2 < INNER / 32) {
            pj_fill(fs, (kt + 2) * 32);
            CP_COMMIT();
        }
        {
            const uint32_t* A = (const uint32_t*)(smf + cs * AS_STAGE);
            const uint32_t* Bm = (const uint32_t*)(smf + PJ_BS_BASE + cs * PJ_BS_STAGE);
#pragma unroll
            for (int ks = 0; ks < 4; ks++) {
                const int kk = ks * 8;
                uint32_t a[2][4];
#pragma unroll
                for (int mt = 0; mt < 2; mt++) {
                    const int row = m_base + mt * 16 + qr;
                    a[mt][0] = A[row * ASTRIDE + kk + qc];
                    a[mt][1] = A[(row + 8) * ASTRIDE + kk + qc];
                    a[mt][2] = A[row * ASTRIDE + kk + 4 + qc];
                    a[mt][3] = A[(row + 8) * ASTRIDE + kk + 4 + qc];
                }
#pragma unroll
                for (int j = 0; j < 4; j++) {
                    uint32_t b[2];
                    const int col = n_base + j * 8 + qr;
                    b[0] = Bm[(kk + qc) * PJ_BSTRIDE + col];
                    b[1] = Bm[(kk + 4 + qc) * PJ_BSTRIDE + col];
#pragma unroll
                    for (int mt = 0; mt < 2; mt++) mma_tf32(acc[mt][j], a[mt], b);
                }
            }
        }
        cs = (cs == 2) ? 0 : cs + 1;
        fs = (fs == 2) ? 0 : fs + 1;
    }

#pragma unroll
    for (int mt = 0; mt < 2; mt++) {
#pragma unroll
        for (int j = 0; j < 4; j++) {
            const int row0 = bm + m_base + mt * 16 + qr;
            const int col0 = bn + n_base + j * 8 + 2 * qc;
            out[(size_t)row0 * DIM + col0]           = acc[mt][j][0] + bp[col0];
            out[(size_t)row0 * DIM + col0 + 1]       = acc[mt][j][1] + bp[col0 + 1];
            out[(size_t)(row0 + 8) * DIM + col0]     = acc[mt][j][2] + bp[col0];
            out[(size_t)(row0 + 8) * DIM + col0 + 1] = acc[mt][j][3] + bp[col0 + 1];
        }
    }
}

// ---------------------------------------------------------------------------
extern "C" void kernel_launch(void* const* d_in, const int* in_sizes, int n_in,
                              void* d_out, int out_size) {
    const float* x  = (const float*)d_in[0];
    const float* Wq = (const float*)d_in[1];
    const float* Wk = (const float*)d_in[2];
    const float* Wv = (const float*)d_in[3];
    const float* Wp = (const float*)d_in[4];
    const float* bp = (const float*)d_in[5];
    float* out = (float*)d_out;

    int dev = 0, sms = 148;
    cudaGetDevice(&dev);
    cudaDeviceGetAttribute(&sms, cudaDevAttrMultiProcessorCount, dev);
    const int slots = 2 * sms;

    const int gemm_smem  = GEMM_SMEM_FLOATS * (int)sizeof(float);   // 107520
    const int flash_smem = FLASH_SMEM_U * (int)sizeof(uint32_t);    // 73728
    const int proj_smem  = PJ_SMEM_FLOATS * (int)sizeof(float);     // 82944
    cudaFuncSetAttribute(qkv_kernel,
                         cudaFuncAttributeMaxDynamicSharedMemorySize, gemm_smem);
    cudaFuncSetAttribute(flash_kernel,
                         cudaFuncAttributeMaxDynamicSharedMemorySize, flash_smem);
    cudaFuncSetAttribute(proj_kernel,
                         cudaFuncAttributeMaxDynamicSharedMemorySize, proj_smem);

    // 0) tf32-round x and weights into scratch
    round_kernel<<<(NXF + 4 * NWF) / 1024, 256>>>(x, Wq, Wk, Wv, Wp);

    // 1) QKV projections (persistent)
    const int g1 = (QKV_UNITS < slots) ? QKV_UNITS : slots;
    qkv_kernel<<<g1, 256, gemm_smem>>>();

    // 2) flash attention (persistent)
    const int g2 = (FLASH_UNITS < slots) ? FLASH_UNITS : slots;
    flash_kernel<<<g2, 256, flash_smem>>>();

    // 3) output projection + bias (128x64 tiles, non-persistent)
    proj_kernel<<<dim3(DIM / 64, MROWS / 128), 256, proj_smem>>>(bp, out);
}

// round 15
// speedup vs baseline: 1.0323x; 1.0323x over previous
#include <cuda_runtime.h>
#include <cuda_bf16.h>
#include <math.h>
#include <stdint.h>

// Problem constants
#define Bb     4
#define SEQ    2048
#define DIM    768
#define NH     12
#define DH     64
#define INNER  768
#define MROWS  (Bb * SEQ)   // 8192
#define NWF    (DIM * INNER)      // 589824 floats per weight

// Scratch (module-static device memory; allocation-free)
__device__ float g_w[4 * NWF];                // tf32-rounded Wq,Wk,Wv,Wp
__device__ __align__(16) __nv_bfloat16 g_qb[Bb * NH * SEQ * DH];  // *log2e/8
__device__ __align__(16) __nv_bfloat16 g_kb[Bb * NH * SEQ * DH];  // [b][h][n][dh]
__device__ __align__(16) __nv_bfloat16 g_vt[Bb * NH * DH * SEQ];  // [b][h][dh][n]
__device__ float g_att[MROWS * INNER];        // attention out (tf32), [b*n][h*64+dh]

// ---------------------------------------------------------------------------
// Helpers
// ---------------------------------------------------------------------------
__device__ __forceinline__ float tf32r(float x) {
    uint32_t u;
    asm("cvt.rna.tf32.f32 %0, %1;" : "=r"(u) : "f"(x));
    return __uint_as_float(u);
}

__device__ __forceinline__ void mma_tf32(float d[4], const uint32_t a[4],
                                         const uint32_t b[2]) {
    asm volatile(
        "mma.sync.aligned.m16n8k8.row.col.f32.tf32.tf32.f32 "
        "{%0,%1,%2,%3}, {%4,%5,%6,%7}, {%8,%9}, {%0,%1,%2,%3};"
        : "+f"(d[0]), "+f"(d[1]), "+f"(d[2]), "+f"(d[3])
        : "r"(a[0]), "r"(a[1]), "r"(a[2]), "r"(a[3]), "r"(b[0]), "r"(b[1]));
}

__device__ __forceinline__ void mma_bf16(float d[4], const uint32_t a[4],
                                         const uint32_t b[2]) {
    asm volatile(
        "mma.sync.aligned.m16n8k16.row.col.f32.bf16.bf16.f32 "
        "{%0,%1,%2,%3}, {%4,%5,%6,%7}, {%8,%9}, {%0,%1,%2,%3};"
        : "+f"(d[0]), "+f"(d[1]), "+f"(d[2]), "+f"(d[3])
        : "r"(a[0]), "r"(a[1]), "r"(a[2]), "r"(a[3]), "r"(b[0]), "r"(b[1]));
}

// Warp-collective: load 4 8x8 b16 matrices.
__device__ __forceinline__ void ldmatrix_x4(uint32_t& r0, uint32_t& r1,
                                            uint32_t& r2, uint32_t& r3,
                                            uint32_t saddr) {
    asm volatile(
        "ldmatrix.sync.aligned.m8n8.x4.shared.b16 {%0,%1,%2,%3}, [%4];"
        : "=r"(r0), "=r"(r1), "=r"(r2), "=r"(r3) : "r"(saddr));
}

__device__ __forceinline__ uint32_t pack_bf16(float lo, float hi) {
    __nv_bfloat162 h = __floats2bfloat162_rn(lo, hi);
    return *(uint32_t*)&h;
}

__device__ __forceinline__ void cp16(uint32_t saddr, const void* gaddr) {
    asm volatile("cp.async.cg.shared.global [%0], [%1], 16;" :: "r"(saddr), "l"(gaddr));
}
#define CP_COMMIT()  asm volatile("cp.async.commit_group;")
#define CP_WAIT1()   asm volatile("cp.async.wait_group 1;" ::: "memory")
#define CP_WAIT0()   asm volatile("cp.async.wait_group 0;" ::: "memory")

// ---------------------------------------------------------------------------
// Kernel 0: round the 4 weight matrices to tf32 (x is consumed raw; HMMA
// truncates fp32->tf32 in hardware).
// ---------------------------------------------------------------------------
__global__ void round_kernel(const float* __restrict__ Wq,
                             const float* __restrict__ Wk,
                             const float* __restrict__ Wv,
                             const float* __restrict__ Wp) {
    const int j = (blockIdx.x * 256 + threadIdx.x) * 4;
    const int w = j / NWF;
    const int off = j - w * NWF;
    const float* src = (w == 0) ? Wq : (w == 1) ? Wk : (w == 2) ? Wv : Wp;
    float4 v = *(const float4*)&src[off];
    v.x = tf32r(v.x); v.y = tf32r(v.y); v.z = tf32r(v.z); v.w = tf32r(v.w);
    *(float4*)&g_w[w * NWF + off] = v;
}

// ---------------------------------------------------------------------------
// GEMM smem geometry (qkv & proj): BM=128, BN=128, BK=32, 3-stage cp.async.
// ---------------------------------------------------------------------------
#define ASTRIDE   36
#define BSTRIDE   136
#define AS_STAGE  (128 * ASTRIDE)          // 4608 floats
#define BS_BASE   (3 * AS_STAGE)           // 13824
#define BS_STAGE  (32 * BSTRIDE)           // 4352
#define GEMM_SMEM_FLOATS (BS_BASE + 3 * BS_STAGE)   // 26880 -> 107520 B

__device__ __forceinline__ void gemm_fill(uint32_t su, int st, int k0,
                                          const float* __restrict__ gA, int bm,
                                          const float* __restrict__ gB, int bn,
                                          int t) {
#pragma unroll
    for (int i = 0; i < 4; i++) {
        const int lin = t + i * 256;
        const int row = lin >> 3;
        const int col = (lin & 7) * 4;
        cp16(su + (uint32_t)(st * AS_STAGE + row * ASTRIDE + col) * 4,
             &gA[(size_t)(bm + row) * DIM + k0 + col]);
    }
#pragma unroll
    for (int i = 0; i < 4; i++) {
        const int lin = t + i * 256;
        const int row = lin >> 5;
        const int col = (lin & 31) * 4;
        cp16(su + (uint32_t)(BS_BASE + st * BS_STAGE + row * BSTRIDE + col) * 4,
             &gB[(size_t)(k0 + row) * INNER + bn + col]);
    }
}

__device__ __forceinline__ void gemm_compute(const float* __restrict__ smf, int st,
                                             int m_base, int n_base, int qr, int qc,
                                             float acc[2][8][4]) {
    const uint32_t* A = (const uint32_t*)(smf + st * AS_STAGE);
    const uint32_t* Bm = (const uint32_t*)(smf + BS_BASE + st * BS_STAGE);
#pragma unroll
    for (int ks = 0; ks < 4; ks++) {
        const int kk = ks * 8;
        uint32_t a[2][4];
#pragma unroll
        for (int mt = 0; mt < 2; mt++) {
            const int row = m_base + mt * 16 + qr;
            a[mt][0] = A[row * ASTRIDE + kk + qc];
            a[mt][1] = A[(row + 8) * ASTRIDE + kk + qc];
            a[mt][2] = A[row * ASTRIDE + kk + 4 + qc];
            a[mt][3] = A[(row + 8) * ASTRIDE + kk + 4 + qc];
        }
#pragma unroll
        for (int j = 0; j < 8; j++) {
            uint32_t b[2];
            const int col = n_base + j * 8 + qr;
            b[0] = Bm[(kk + qc) * BSTRIDE + col];
            b[1] = Bm[(kk + 4 + qc) * BSTRIDE + col];
#pragma unroll
            for (int mt = 0; mt < 2; mt++) mma_tf32(acc[mt][j], a[mt], b);
        }
    }
}

// ---------------------------------------------------------------------------
// Kernel 1: persistent fused QKV projection (tf32 MMA), bf16 outputs.
// A = raw x (hardware-truncated to tf32), B = RNA-rounded weights.
// ---------------------------------------------------------------------------
#define QSCALE 0.1803368801111204f   // 0.125 * log2(e)
#define QKV_UNITS (3 * 64 * 6)       // 1152

__global__ __launch_bounds__(256, 2) void qkv_kernel(const float* __restrict__ x) {
    extern __shared__ float smf[];
    const uint32_t su = (uint32_t)__cvta_generic_to_shared(smf);

    const int t  = threadIdx.x;
    const int warp = t >> 5;
    const int lane = t & 31;
    const int m_base = (warp >> 1) * 32;
    const int n_base = (warp & 1) * 64;
    const int qr = lane >> 2;
    const int qc = lane & 3;

    for (int unit = blockIdx.x; unit < QKV_UNITS; unit += gridDim.x) {
        __syncthreads();

        const int z      = unit / 384;
        const int rem    = unit - z * 384;
        const int bm     = (rem / 6) * 128;
        const int bn     = (rem % 6) * 128;

        const float* W;
        __nv_bfloat16* outp;
        float scale = 1.0f;
        bool transpose = false;
        if (z == 0)      { W = g_w;           outp = g_qb; scale = QSCALE; }
        else if (z == 1) { W = g_w + NWF;     outp = g_kb; }
        else             { W = g_w + 2 * NWF; outp = g_vt; transpose = true; }

        float acc[2][8][4];
#pragma unroll
        for (int mt = 0; mt < 2; mt++)
#pragma unroll
            for (int j = 0; j < 8; j++)
#pragma unroll
                for (int e = 0; e < 4; e++) acc[mt][j][e] = 0.0f;

        gemm_fill(su, 0, 0, x, bm, W, bn, t);
        CP_COMMIT();
        gemm_fill(su, 1, 32, x, bm, W, bn, t);
        CP_COMMIT();

        int cs = 0, fs = 2;
        for (int kt = 0; kt < DIM / 32; kt++) {
            if (kt + 1 < DIM / 32) { CP_WAIT1(); } else { CP_WAIT0(); }
            __syncthreads();
            if (kt + 2 < DIM / 32) {
                gemm_fill(su, fs, (kt + 2) * 32, x, bm, W, bn, t);
                CP_COMMIT();
            }
            gemm_compute(smf, cs, m_base, n_base, qr, qc, acc);
            cs = (cs == 2) ? 0 : cs + 1;
            fs = (fs == 2) ? 0 : fs + 1;
        }

#pragma unroll
        for (int mt = 0; mt < 2; mt++) {
#pragma unroll
            for (int j = 0; j < 8; j++) {
#pragma unroll
                for (int e = 0; e < 4; e++) {
                    const int row = bm + m_base + mt * 16 + qr + (e >= 2 ? 8 : 0);
                    const int col = bn + n_base + j * 8 + 2 * qc + (e & 1);
                    const int bidx = row >> 11;
                    const int n    = row & 2047;
                    const int h    = col >> 6;
                    const int dh   = col & 63;
                    const size_t idx = transpose
                        ? ((((size_t)bidx * NH + h) * DH) + dh) * SEQ + n
                        : ((((size_t)bidx * NH + h) * SEQ) + n) * DH + dh;
                    outp[idx] = __float2bfloat16(acc[mt][j][e] * scale);
                }
            }
        }
    }
}

// ---------------------------------------------------------------------------
// Kernel 2: persistent flash attention (r12-proven version, unchanged)
// ---------------------------------------------------------------------------
#define UKSTRIDE   36
#define KV_STAGE_U (64 * UKSTRIDE)                 // 2304
#define VS_BASE_U  (3 * KV_STAGE_U)                // 6912
#define PS_BASE_U  (VS_BASE_U + 3 * KV_STAGE_U)    // 13824
#define FLASH_SMEM_U (PS_BASE_U + 128 * UKSTRIDE)  // 18432 -> 73728 B
#define FLASH_UNITS (Bb * NH * (SEQ / 128))        // 768

__global__ __launch_bounds__(256, 2) void flash_kernel() {
    extern __shared__ uint32_t smu[];
    const uint32_t su = (uint32_t)__cvta_generic_to_shared(smu);
    uint32_t* Psu = smu + PS_BASE_U;

    const int t  = threadIdx.x;
    const int warp = t >> 5;
    const int lane = t & 31;
    const int qr = lane >> 2;
    const int qc = lane & 3;
    const int wrow = warp * 16;

    const int lm_row = (lane & 7) + ((lane & 16) >> 1);
    const int lm_col = (lane & 8) >> 1;
    const uint32_t lm_off = (uint32_t)(lm_row * UKSTRIDE + lm_col) * 4;

    for (int unit = blockIdx.x; unit < FLASH_UNITS; unit += gridDim.x) {
        __syncthreads();

        const int qt = unit & 15;
        const int bh = unit >> 4;
        const int h  = bh % NH;
        const int b  = bh / NH;

        const size_t head_nd = ((size_t)b * NH + h) * SEQ * DH;
        const __nv_bfloat16* qbase  = g_qb + head_nd + (size_t)qt * 128 * DH;
        const __nv_bfloat16* kbase  = g_kb + head_nd;
        const __nv_bfloat16* vtbase = g_vt + head_nd;

#pragma unroll
        for (int st = 0; st < 2; st++) {
            const __nv_bfloat16* ktile = kbase + (size_t)st * 64 * DH;
            const __nv_bfloat16* vtile = vtbase + (size_t)st * 64;
#pragma unroll
            for (int i = 0; i < 2; i++) {
                const int lin = t + i * 256;
                const int row = lin >> 3;
                const int ch  = lin & 7;
                cp16(su + (uint32_t)(st * KV_STAGE_U + row * UKSTRIDE + ch * 4) * 4,
                     ktile + row * DH + ch * 8);
                cp16(su + (uint32_t)(VS_BASE_U + st * KV_STAGE_U + row * UKSTRIDE + ch * 4) * 4,
                     vtile + (size_t)row * SEQ + ch * 8);
            }
            CP_COMMIT();
        }

#pragma unroll
        for (int i = 0; i < 4; i++) {
            const int lin = t + i * 256;
            const int row = lin >> 3;
            const int ch  = lin & 7;
            *(float4*)&Psu[row * UKSTRIDE + ch * 4] =
                *(const float4*)&qbase[row * DH + ch * 8];
        }
        __syncthreads();

        uint32_t qf[4][4];
#pragma unroll
        for (int ks = 0; ks < 4; ks++) {
            qf[ks][0] = Psu[(wrow + qr) * UKSTRIDE + ks * 8 + qc];
            qf[ks][1] = Psu[(wrow + qr + 8) * UKSTRIDE + ks * 8 + qc];
            qf[ks][2] = Psu[(wrow + qr) * UKSTRIDE + ks * 8 + 4 + qc];
            qf[ks][3] = Psu[(wrow + qr + 8) * UKSTRIDE + ks * 8 + 4 + qc];
        }

        float o[8][4];
#pragma unroll
        for (int j = 0; j < 8; j++)
#pragma unroll
            for (int e = 0; e < 4; e++) o[j][e] = 0.0f;
        float m_lo = -INFINITY, m_hi = -INFINITY, l_lo = 0.0f, l_hi = 0.0f;

        int cs = 0, fs = 2;
        for (int kt = 0; kt < SEQ / 64; kt++) {
            if (kt + 1 < SEQ / 64) { CP_WAIT1(); } else { CP_WAIT0(); }
            __syncthreads();
            if (kt + 2 < SEQ / 64) {
                const __nv_bfloat16* ktile = kbase + (size_t)(kt + 2) * 64 * DH;
                const __nv_bfloat16* vtile = vtbase + (size_t)(kt + 2) * 64;
#pragma unroll
                for (int i = 0; i < 2; i++) {
                    const int lin = t + i * 256;
                    const int row = lin >> 3;
                    const int ch  = lin & 7;
                    cp16(su + (uint32_t)(fs * KV_STAGE_U + row * UKSTRIDE + ch * 4) * 4,
                         ktile + row * DH + ch * 8);
                    cp16(su + (uint32_t)(VS_BASE_U + fs * KV_STAGE_U + row * UKSTRIDE + ch * 4) * 4,
                         vtile + (size_t)row * SEQ + ch * 8);
                }
                CP_COMMIT();
            }

            const uint32_t k_lm = su + (uint32_t)(cs * KV_STAGE_U) * 4 + lm_off;
            const uint32_t v_lm = su + (uint32_t)(VS_BASE_U + cs * KV_STAGE_U) * 4 + lm_off;

            float s[8][4];
#pragma unroll
            for (int j = 0; j < 8; j++)
#pragma unroll
                for (int e = 0; e < 4; e++) s[j][e] = 0.0f;
#pragma unroll
            for (int ks = 0; ks < 4; ks++) {
#pragma unroll
                for (int jp = 0; jp < 4; jp++) {
                    uint32_t b0, b1, b2, b3;
                    ldmatrix_x4(b0, b1, b2, b3,
                                k_lm + (uint32_t)(jp * 16 * UKSTRIDE + ks * 8) * 4);
                    uint32_t br0[2] = {b0, b1};
                    uint32_t br1[2] = {b2, b3};
                    mma_bf16(s[2 * jp],     qf[ks], br0);
                    mma_bf16(s[2 * jp + 1], qf[ks], br1);
                }
            }

            float mx_lo = m_lo, mx_hi = m_hi;
#pragma unroll
            for (int j = 0; j < 8; j++) {
                mx_lo = fmaxf(mx_lo, fmaxf(s[j][0], s[j][1]));
                mx_hi = fmaxf(mx_hi, fmaxf(s[j][2], s[j][3]));
            }
            mx_lo = fmaxf(mx_lo, __shfl_xor_sync(0xffffffffu, mx_lo, 1));
            mx_lo = fmaxf(mx_lo, __shfl_xor_sync(0xffffffffu, mx_lo, 2));
            mx_hi = fmaxf(mx_hi, __shfl_xor_sync(0xffffffffu, mx_hi, 1));
            mx_hi = fmaxf(mx_hi, __shfl_xor_sync(0xffffffffu, mx_hi, 2));

            const float c_lo = exp2f(m_lo - mx_lo);
            const float c_hi = exp2f(m_hi - mx_hi);
            float sum_lo = 0.0f, sum_hi = 0.0f;
#pragma unroll
            for (int j = 0; j < 8; j++) {
                s[j][0] = exp2f(s[j][0] - mx_lo);
                s[j][1] = exp2f(s[j][1] - mx_lo);
                s[j][2] = exp2f(s[j][2] - mx_hi);
                s[j][3] = exp2f(s[j][3] - mx_hi);
                sum_lo += s[j][0] + s[j][1];
                sum_hi += s[j][2] + s[j][3];
            }
            sum_lo += __shfl_xor_sync(0xffffffffu, sum_lo, 1);
            sum_lo += __shfl_xor_sync(0xffffffffu, sum_lo, 2);
            sum_hi += __shfl_xor_sync(0xffffffffu, sum_hi, 1);
            sum_hi += __shfl_xor_sync(0xffffffffu, sum_hi, 2);
            l_lo = l_lo * c_lo + sum_lo;
            l_hi = l_hi * c_hi + sum_hi;
            m_lo = mx_lo;
            m_hi = mx_hi;

#pragma unroll
            for (int j = 0; j < 8; j++) {
                o[j][0] *= c_lo; o[j][1] *= c_lo;
                o[j][2] *= c_hi; o[j][3] *= c_hi;
            }

#pragma unroll
            for (int ks = 0; ks < 4; ks++) {
                uint32_t a[4];
                a[0] = pack_bf16(s[2 * ks][0],     s[2 * ks][1]);
                a[1] = pack_bf16(s[2 * ks][2],     s[2 * ks][3]);
                a[2] = pack_bf16(s[2 * ks + 1][0], s[2 * ks + 1][1]);
                a[3] = pack_bf16(s[2 * ks + 1][2], s[2 * ks + 1][3]);
#pragma unroll
                for (int jp = 0; jp < 4; jp++) {
                    uint32_t b0, b1, b2, b3;
                    ldmatrix_x4(b0, b1, b2, b3,
                                v_lm + (uint32_t)(jp * 16 * UKSTRIDE + ks * 8) * 4);
                    uint32_t br0[2] = {b0, b1};
                    uint32_t br1[2] = {b2, b3};
                    mma_bf16(o[2 * jp],     a, br0);
                    mma_bf16(o[2 * jp + 1], a, br1);
                }
            }

            cs = (cs == 2) ? 0 : cs + 1;
            fs = (fs == 2) ? 0 : fs + 1;
        }

        const float inv_lo = 1.0f / l_lo;
        const float inv_hi = 1.0f / l_hi;
        const int n_lo = qt * 128 + wrow + qr;
#pragma unroll
        for (int j = 0; j < 8; j++) {
            const int col = h * 64 + j * 8 + 2 * qc;
            *(float2*)&g_att[((size_t)b * SEQ + n_lo) * INNER + col] =
                make_float2(tf32r(o[j][0] * inv_lo), tf32r(o[j][1] * inv_lo));
            *(float2*)&g_att[((size_t)b * SEQ + n_lo + 8) * INNER + col] =
                make_float2(tf32r(o[j][2] * inv_hi), tf32r(o[j][3] * inv_hi));
        }
    }
}

// ---------------------------------------------------------------------------
// Kernel 3: output projection (r11-proven: BM=128 x BN=128, non-persistent,
// 3-stage, single barrier per tile).  out = g_att @ g_w[3] + bp
// ---------------------------------------------------------------------------
__global__ __launch_bounds__(256, 2) void proj_kernel(const float* __restrict__ bp,
                                                      float* __restrict__ out) {
    extern __shared__ float smf[];
    const uint32_t su = (uint32_t)__cvta_generic_to_shared(smf);
    const float* Wp = g_w + 3 * (size_t)NWF;

    const int bm = blockIdx.y * 128;
    const int bn = blockIdx.x * 128;
    const int t  = threadIdx.x;
    const int warp = t >> 5;
    const int lane = t & 31;
    const int m_base = (warp >> 1) * 32;
    const int n_base = (warp & 1) * 64;
    const int qr = lane >> 2;
    const int qc = lane & 3;

    float acc[2][8][4];
#pragma unroll
    for (int mt = 0; mt < 2; mt++)
#pragma unroll
        for (int j = 0; j < 8; j++)
#pragma unroll
            for (int e = 0; e < 4; e++) acc[mt][j][e] = 0.0f;

    gemm_fill(su, 0, 0, g_att, bm, Wp, bn, t);
    CP_COMMIT();
    gemm_fill(su, 1, 32, g_att, bm, Wp, bn, t);
    CP_COMMIT();

    int cs = 0, fs = 2;
    for (int kt = 0; kt < INNER / 32; kt++) {
        if (kt + 1 < INNER / 32) { CP_WAIT1(); } else { CP_WAIT0(); }
        __syncthreads();
        if (kt + 2 < INNER / 32) {
            gemm_fill(su, fs, (kt + 2) * 32, g_att, bm, Wp, bn, t);
            CP_COMMIT();
        }
        gemm_compute(smf, cs, m_base, n_base, qr, qc, acc);
        cs = (cs == 2) ? 0 : cs + 1;
        fs = (fs == 2) ? 0 : fs + 1;
    }

#pragma unroll
    for (int mt = 0; mt < 2; mt++) {
#pragma unroll
        for (int j = 0; j < 8; j++) {
            const int row0 = bm + m_base + mt * 16 + qr;
            const int col0 = bn + n_base + j * 8 + 2 * qc;
            out[(size_t)row0 * DIM + col0]           = acc[mt][j][0] + bp[col0];
            out[(size_t)row0 * DIM + col0 + 1]       = acc[mt][j][1] + bp[col0 + 1];
            out[(size_t)(row0 + 8) * DIM + col0]     = acc[mt][j][2] + bp[col0];
            out[(size_t)(row0 + 8) * DIM + col0 + 1] = acc[mt][j][3] + bp[col0 + 1];
        }
    }
}

// ---------------------------------------------------------------------------
extern "C" void kernel_launch(void* const* d_in, const int* in_sizes, int n_in,
                              void* d_out, int out_size) {
    const float* x  = (const float*)d_in[0];
    const float* Wq = (const float*)d_in[1];
    const float* Wk = (const float*)d_in[2];
    const float* Wv = (const float*)d_in[3];
    const float* Wp = (const float*)d_in[4];
    const float* bp = (const float*)d_in[5];
    float* out = (float*)d_out;

    int dev = 0, sms = 148;
    cudaGetDevice(&dev);
    cudaDeviceGetAttribute(&sms, cudaDevAttrMultiProcessorCount, dev);
    const int slots = 2 * sms;

    const int gemm_smem  = GEMM_SMEM_FLOATS * (int)sizeof(float);   // 107520
    const int flash_smem = FLASH_SMEM_U * (int)sizeof(uint32_t);    // 73728
    cudaFuncSetAttribute(qkv_kernel,
                         cudaFuncAttributeMaxDynamicSharedMemorySize, gemm_smem);
    cudaFuncSetAttribute(flash_kernel,
                         cudaFuncAttributeMaxDynamicSharedMemorySize, flash_smem);
    cudaFuncSetAttribute(proj_kernel,
                         cudaFuncAttributeMaxDynamicSharedMemorySize, gemm_smem);

    // 0) tf32-round weights only (x consumed raw; HMMA truncates to tf32)
    round_kernel<<<4 * NWF / 1024, 256>>>(Wq, Wk, Wv, Wp);

    // 1) QKV projections (persistent)
    const int g1 = (QKV_UNITS < slots) ? QKV_UNITS : slots;
    qkv_kernel<<<g1, 256, gemm_smem>>>(x);

    // 2) flash attention (persistent)
    const int g2 = (FLASH_UNITS < slots) ? FLASH_UNITS : slots;
    flash_kernel<<<g2, 256, flash_smem>>>();

    // 3) output projection + bias (non-persistent BN=128)
    proj_kernel<<<dim3(DIM / 128, MROWS / 128), 256, gemm_smem>>>(bp, out);
}

// round 16
// speedup vs baseline: 1.0363x; 1.0039x over previous
#include <cuda_runtime.h>
#include <cuda_bf16.h>
#include <math.h>
#include <stdint.h>

// Problem constants
#define Bb     4
#define SEQ    2048
#define DIM    768
#define NH     12
#define DH     64
#define INNER  768
#define MROWS  (Bb * SEQ)   // 8192
#define NWF    (DIM * INNER)      // 589824 floats per weight

// Scratch (module-static device memory; allocation-free)
__device__ float g_w[4 * NWF];                // tf32-rounded Wq,Wk,Wv,Wp
__device__ __align__(16) __nv_bfloat16 g_qb[Bb * NH * SEQ * DH];  // *log2e/8
__device__ __align__(16) __nv_bfloat16 g_kb[Bb * NH * SEQ * DH];  // [b][h][n][dh]
__device__ __align__(16) __nv_bfloat16 g_vt[Bb * NH * DH * SEQ];  // [b][h][dh][n]
__device__ float g_att[MROWS * INNER];        // attention out (tf32), [b*n][h*64+dh]

// ---------------------------------------------------------------------------
// Helpers
// ---------------------------------------------------------------------------
__device__ __forceinline__ float tf32r(float x) {
    uint32_t u;
    asm("cvt.rna.tf32.f32 %0, %1;" : "=r"(u) : "f"(x));
    return __uint_as_float(u);
}

__device__ __forceinline__ void mma_tf32(float d[4], const uint32_t a[4],
                                         const uint32_t b[2]) {
    asm volatile(
        "mma.sync.aligned.m16n8k8.row.col.f32.tf32.tf32.f32 "
        "{%0,%1,%2,%3}, {%4,%5,%6,%7}, {%8,%9}, {%0,%1,%2,%3};"
        : "+f"(d[0]), "+f"(d[1]), "+f"(d[2]), "+f"(d[3])
        : "r"(a[0]), "r"(a[1]), "r"(a[2]), "r"(a[3]), "r"(b[0]), "r"(b[1]));
}

__device__ __forceinline__ void mma_bf16(float d[4], const uint32_t a[4],
                                         const uint32_t b[2]) {
    asm volatile(
        "mma.sync.aligned.m16n8k16.row.col.f32.bf16.bf16.f32 "
        "{%0,%1,%2,%3}, {%4,%5,%6,%7}, {%8,%9}, {%0,%1,%2,%3};"
        : "+f"(d[0]), "+f"(d[1]), "+f"(d[2]), "+f"(d[3])
        : "r"(a[0]), "r"(a[1]), "r"(a[2]), "r"(a[3]), "r"(b[0]), "r"(b[1]));
}

// Warp-collective: load 4 8x8 b16 matrices.
__device__ __forceinline__ void ldmatrix_x4(uint32_t& r0, uint32_t& r1,
                                            uint32_t& r2, uint32_t& r3,
                                            uint32_t saddr) {
    asm volatile(
        "ldmatrix.sync.aligned.m8n8.x4.shared.b16 {%0,%1,%2,%3}, [%4];"
        : "=r"(r0), "=r"(r1), "=r"(r2), "=r"(r3) : "r"(saddr));
}

__device__ __forceinline__ uint32_t pack_bf16(float lo, float hi) {
    __nv_bfloat162 h = __floats2bfloat162_rn(lo, hi);
    return *(uint32_t*)&h;
}

__device__ __forceinline__ void cp16(uint32_t saddr, const void* gaddr) {
    asm volatile("cp.async.cg.shared.global [%0], [%1], 16;" :: "r"(saddr), "l"(gaddr));
}
#define CP_COMMIT()  asm volatile("cp.async.commit_group;")
#define CP_WAIT1()   asm volatile("cp.async.wait_group 1;" ::: "memory")
#define CP_WAIT0()   asm volatile("cp.async.wait_group 0;" ::: "memory")

// ---------------------------------------------------------------------------
// Kernel 0: round the 4 weight matrices to tf32 (x consumed raw; HMMA
// truncates fp32->tf32 in hardware).
// ---------------------------------------------------------------------------
__global__ void round_kernel(const float* __restrict__ Wq,
                             const float* __restrict__ Wk,
                             const float* __restrict__ Wv,
                             const float* __restrict__ Wp) {
    const int j = (blockIdx.x * 256 + threadIdx.x) * 4;
    const int w = j / NWF;
    const int off = j - w * NWF;
    const float* src = (w == 0) ? Wq : (w == 1) ? Wk : (w == 2) ? Wv : Wp;
    float4 v = *(const float4*)&src[off];
    v.x = tf32r(v.x); v.y = tf32r(v.y); v.z = tf32r(v.z); v.w = tf32r(v.w);
    *(float4*)&g_w[w * NWF + off] = v;
}

// ---------------------------------------------------------------------------
// GEMM smem geometry (qkv & proj): BM=128, BN=128, BK=32, 3-stage cp.async.
// ---------------------------------------------------------------------------
#define ASTRIDE   36
#define BSTRIDE   136
#define AS_STAGE  (128 * ASTRIDE)          // 4608 floats
#define BS_BASE   (3 * AS_STAGE)           // 13824
#define BS_STAGE  (32 * BSTRIDE)           // 4352
#define GEMM_SMEM_FLOATS (BS_BASE + 3 * BS_STAGE)   // 26880 -> 107520 B

// qkv epilogue staging: 128 rows x 68 u32 (64 bf16-pairs + pad) = 34816 B,
// overlaid on the cp.async stages after the mainloop completes.
#define STG_STRIDE 68

__device__ __forceinline__ void gemm_fill(uint32_t su, int st, int k0,
                                          const float* __restrict__ gA, int bm,
                                          const float* __restrict__ gB, int bn,
                                          int t) {
#pragma unroll
    for (int i = 0; i < 4; i++) {
        const int lin = t + i * 256;
        const int row = lin >> 3;
        const int col = (lin & 7) * 4;
        cp16(su + (uint32_t)(st * AS_STAGE + row * ASTRIDE + col) * 4,
             &gA[(size_t)(bm + row) * DIM + k0 + col]);
    }
#pragma unroll
    for (int i = 0; i < 4; i++) {
        const int lin = t + i * 256;
        const int row = lin >> 5;
        const int col = (lin & 31) * 4;
        cp16(su + (uint32_t)(BS_BASE + st * BS_STAGE + row * BSTRIDE + col) * 4,
             &gB[(size_t)(k0 + row) * INNER + bn + col]);
    }
}

__device__ __forceinline__ void gemm_compute(const float* __restrict__ smf, int st,
                                             int m_base, int n_base, int qr, int qc,
                                             float acc[2][8][4]) {
    const uint32_t* A = (const uint32_t*)(smf + st * AS_STAGE);
    const uint32_t* Bm = (const uint32_t*)(smf + BS_BASE + st * BS_STAGE);
#pragma unroll
    for (int ks = 0; ks < 4; ks++) {
        const int kk = ks * 8;
        uint32_t a[2][4];
#pragma unroll
        for (int mt = 0; mt < 2; mt++) {
            const int row = m_base + mt * 16 + qr;
            a[mt][0] = A[row * ASTRIDE + kk + qc];
            a[mt][1] = A[(row + 8) * ASTRIDE + kk + qc];
            a[mt][2] = A[row * ASTRIDE + kk + 4 + qc];
            a[mt][3] = A[(row + 8) * ASTRIDE + kk + 4 + qc];
        }
#pragma unroll
        for (int j = 0; j < 8; j++) {
            uint32_t b[2];
            const int col = n_base + j * 8 + qr;
            b[0] = Bm[(kk + qc) * BSTRIDE + col];
            b[1] = Bm[(kk + 4 + qc) * BSTRIDE + col];
#pragma unroll
            for (int mt = 0; mt < 2; mt++) mma_tf32(acc[mt][j], a[mt], b);
        }
    }
}

// ---------------------------------------------------------------------------
// Kernel 1: persistent fused QKV projection (tf32 MMA), bf16 outputs with
// smem-staged COALESCED stores.
// ---------------------------------------------------------------------------
#define QSCALE 0.1803368801111204f   // 0.125 * log2(e)
#define QKV_UNITS (3 * 64 * 6)       // 1152

__global__ __launch_bounds__(256, 2) void qkv_kernel(const float* __restrict__ x) {
    extern __shared__ float smf[];
    const uint32_t su = (uint32_t)__cvta_generic_to_shared(smf);
    uint32_t* stageu = (uint32_t*)smf;

    const int t  = threadIdx.x;
    const int warp = t >> 5;
    const int lane = t & 31;
    const int m_base = (warp >> 1) * 32;
    const int n_base = (warp & 1) * 64;
    const int qr = lane >> 2;
    const int qc = lane & 3;

    for (int unit = blockIdx.x; unit < QKV_UNITS; unit += gridDim.x) {
        __syncthreads();   // staging/ smem of previous unit fully consumed

        const int z      = unit / 384;
        const int rem    = unit - z * 384;
        const int bm     = (rem / 6) * 128;
        const int bn     = (rem % 6) * 128;

        const float* W;
        __nv_bfloat16* outp;
        float scale = 1.0f;
        if (z == 0)      { W = g_w;           outp = g_qb; scale = QSCALE; }
        else if (z == 1) { W = g_w + NWF;     outp = g_kb; }
        else             { W = g_w + 2 * NWF; outp = g_vt; }

        float acc[2][8][4];
#pragma unroll
        for (int mt = 0; mt < 2; mt++)
#pragma unroll
            for (int j = 0; j < 8; j++)
#pragma unroll
                for (int e = 0; e < 4; e++) acc[mt][j][e] = 0.0f;

        gemm_fill(su, 0, 0, x, bm, W, bn, t);
        CP_COMMIT();
        gemm_fill(su, 1, 32, x, bm, W, bn, t);
        CP_COMMIT();

        int cs = 0, fs = 2;
        for (int kt = 0; kt < DIM / 32; kt++) {
            if (kt + 1 < DIM / 32) { CP_WAIT1(); } else { CP_WAIT0(); }
            __syncthreads();
            if (kt + 2 < DIM / 32) {
                gemm_fill(su, fs, (kt + 2) * 32, x, bm, W, bn, t);
                CP_COMMIT();
            }
            gemm_compute(smf, cs, m_base, n_base, qr, qc, acc);
            cs = (cs == 2) ? 0 : cs + 1;
            fs = (fs == 2) ? 0 : fs + 1;
        }

        // ---- Epilogue: stage tile in smem (bf16 pairs), then coalesced STG ----
        __syncthreads();   // all warps done with cp.async stages before overlay
#pragma unroll
        for (int mt = 0; mt < 2; mt++) {
#pragma unroll
            for (int j = 0; j < 8; j++) {
                const int pr = (n_base + j * 8) / 2 + qc;   // u32 pair column
                const int r0 = m_base + mt * 16 + qr;
                stageu[r0 * STG_STRIDE + pr] =
                    pack_bf16(acc[mt][j][0] * scale, acc[mt][j][1] * scale);
                stageu[(r0 + 8) * STG_STRIDE + pr] =
                    pack_bf16(acc[mt][j][2] * scale, acc[mt][j][3] * scale);
            }
        }
        __syncthreads();

        if (z != 2) {
            // q/k: row-major [n][dh]; 2048 16B chunks, 8/thread, coalesced.
#pragma unroll
            for (int i = 0; i < 8; i++) {
                const int c   = t + i * 256;
                const int row = c >> 4;            // 0..127
                const int ch  = c & 15;            // 16B chunk within row
                const int col0 = ch * 8;
                uint32_t v[4];
#pragma unroll
                for (int p = 0; p < 4; p++)
                    v[p] = stageu[row * STG_STRIDE + ch * 4 + p];
                const int rowg = bm + row;
                const int bidx = rowg >> 11;
                const int n    = rowg & 2047;
                const int colg = bn + col0;
                const int h    = colg >> 6;
                const int dh   = colg & 63;
                float4* dst = (float4*)&outp[((((size_t)bidx * NH + h) * SEQ) + n) * DH + dh];
                *dst = make_float4(__uint_as_float(v[0]), __uint_as_float(v[1]),
                                   __uint_as_float(v[2]), __uint_as_float(v[3]));
            }
        } else {
            // v: transposed [dh][n]; per-thread column gather, coalesced 16B store.
#pragma unroll
            for (int i = 0; i < 8; i++) {
                const int c     = t + i * 256;
                const int dhcol = c >> 4;          // 0..127 (tile column)
                const int nch   = c & 15;          // 8-row chunk along n
                const int n0    = nch * 8;
                const int sh    = (dhcol & 1) * 16;
                const int pcol  = dhcol >> 1;
                uint32_t uv[8];
#pragma unroll
                for (int kk = 0; kk < 8; kk++) {
                    const int k = kk ^ (nch & 7);  // stagger -> <=2-way conflicts
                    uv[k] = stageu[(n0 + k) * STG_STRIDE + pcol];
                }
                uint32_t pk[4];
#pragma unroll
                for (int p = 0; p < 4; p++) {
                    const uint32_t v0 = (uv[2 * p]     >> sh) & 0xffffu;
                    const uint32_t v1 = (uv[2 * p + 1] >> sh) & 0xffffu;
                    pk[p] = v0 | (v1 << 16);
                }
                const int rowg = bm + n0;          // global n of first element
                const int bidx = rowg >> 11;
                const int n    = rowg & 2047;
                const int colg = bn + dhcol;
                const int h    = colg >> 6;
                const int dh   = colg & 63;
                float4* dst = (float4*)&outp[((((size_t)bidx * NH + h) * DH) + dh) * SEQ + n];
                *dst = make_float4(__uint_as_float(pk[0]), __uint_as_float(pk[1]),
                                   __uint_as_float(pk[2]), __uint_as_float(pk[3]));
            }
        }
    }
}

// ---------------------------------------------------------------------------
// Kernel 2: persistent flash attention (r12-proven version, unchanged)
// ---------------------------------------------------------------------------
#define UKSTRIDE   36
#define KV_STAGE_U (64 * UKSTRIDE)                 // 2304
#define VS_BASE_U  (3 * KV_STAGE_U)                // 6912
#define PS_BASE_U  (VS_BASE_U + 3 * KV_STAGE_U)    // 13824
#define FLASH_SMEM_U (PS_BASE_U + 128 * UKSTRIDE)  // 18432 -> 73728 B
#define FLASH_UNITS (Bb * NH * (SEQ / 128))        // 768

__global__ __launch_bounds__(256, 2) void flash_kernel() {
    extern __shared__ uint32_t smu[];
    const uint32_t su = (uint32_t)__cvta_generic_to_shared(smu);
    uint32_t* Psu = smu + PS_BASE_U;

    const int t  = threadIdx.x;
    const int warp = t >> 5;
    const int lane = t & 31;
    const int qr = lane >> 2;
    const int qc = lane & 3;
    const int wrow = warp * 16;

    const int lm_row = (lane & 7) + ((lane & 16) >> 1);
    const int lm_col = (lane & 8) >> 1;
    const uint32_t lm_off = (uint32_t)(lm_row * UKSTRIDE + lm_col) * 4;

    for (int unit = blockIdx.x; unit < FLASH_UNITS; unit += gridDim.x) {
        __syncthreads();

        const int qt = unit & 15;
        const int bh = unit >> 4;
        const int h  = bh % NH;
        const int b  = bh / NH;

        const size_t head_nd = ((size_t)b * NH + h) * SEQ * DH;
        const __nv_bfloat16* qbase  = g_qb + head_nd + (size_t)qt * 128 * DH;
        const __nv_bfloat16* kbase  = g_kb + head_nd;
        const __nv_bfloat16* vtbase = g_vt + head_nd;

#pragma unroll
        for (int st = 0; st < 2; st++) {
            const __nv_bfloat16* ktile = kbase + (size_t)st * 64 * DH;
            const __nv_bfloat16* vtile = vtbase + (size_t)st * 64;
#pragma unroll
            for (int i = 0; i < 2; i++) {
                const int lin = t + i * 256;
                const int row = lin >> 3;
                const int ch  = lin & 7;
                cp16(su + (uint32_t)(st * KV_STAGE_U + row * UKSTRIDE + ch * 4) * 4,
                     ktile + row * DH + ch * 8);
                cp16(su + (uint32_t)(VS_BASE_U + st * KV_STAGE_U + row * UKSTRIDE + ch * 4) * 4,
                     vtile + (size_t)row * SEQ + ch * 8);
            }
            CP_COMMIT();
        }

#pragma unroll
        for (int i = 0; i < 4; i++) {
            const int lin = t + i * 256;
            const int row = lin >> 3;
            const int ch  = lin & 7;
            *(float4*)&Psu[row * UKSTRIDE + ch * 4] =
                *(const float4*)&qbase[row * DH + ch * 8];
        }
        __syncthreads();

        uint32_t qf[4][4];
#pragma unroll
        for (int ks = 0; ks < 4; ks++) {
            qf[ks][0] = Psu[(wrow + qr) * UKSTRIDE + ks * 8 + qc];
            qf[ks][1] = Psu[(wrow + qr + 8) * UKSTRIDE + ks * 8 + qc];
            qf[ks][2] = Psu[(wrow + qr) * UKSTRIDE + ks * 8 + 4 + qc];
            qf[ks][3] = Psu[(wrow + qr + 8) * UKSTRIDE + ks * 8 + 4 + qc];
        }

        float o[8][4];
#pragma unroll
        for (int j = 0; j < 8; j++)
#pragma unroll
            for (int e = 0; e < 4; e++) o[j][e] = 0.0f;
        float m_lo = -INFINITY, m_hi = -INFINITY, l_lo = 0.0f, l_hi = 0.0f;

        int cs = 0, fs = 2;
        for (int kt = 0; kt < SEQ / 64; kt++) {
            if (kt + 1 < SEQ / 64) { CP_WAIT1(); } else { CP_WAIT0(); }
            __syncthreads();
            if (kt + 2 < SEQ / 64) {
                const __nv_bfloat16* ktile = kbase + (size_t)(kt + 2) * 64 * DH;
                const __nv_bfloat16* vtile = vtbase + (size_t)(kt + 2) * 64;
#pragma unroll
                for (int i = 0; i < 2; i++) {
                    const int lin = t + i * 256;
                    const int row = lin >> 3;
                    const int ch  = lin & 7;
                    cp16(su + (uint32_t)(fs * KV_STAGE_U + row * UKSTRIDE + ch * 4) * 4,
                         ktile + row * DH + ch * 8);
                    cp16(su + (uint32_t)(VS_BASE_U + fs * KV_STAGE_U + row * UKSTRIDE + ch * 4) * 4,
                         vtile + (size_t)row * SEQ + ch * 8);
                }
                CP_COMMIT();
            }

            const uint32_t k_lm = su + (uint32_t)(cs * KV_STAGE_U) * 4 + lm_off;
            const uint32_t v_lm = su + (uint32_t)(VS_BASE_U + cs * KV_STAGE_U) * 4 + lm_off;

            float s[8][4];
#pragma unroll
            for (int j = 0; j < 8; j++)
#pragma unroll
                for (int e = 0; e < 4; e++) s[j][e] = 0.0f;
#pragma unroll
            for (int ks = 0; ks < 4; ks++) {
#pragma unroll
                for (int jp = 0; jp < 4; jp++) {
                    uint32_t b0, b1, b2, b3;
                    ldmatrix_x4(b0, b1, b2, b3,
                                k_lm + (uint32_t)(jp * 16 * UKSTRIDE + ks * 8) * 4);
                    uint32_t br0[2] = {b0, b1};
                    uint32_t br1[2] = {b2, b3};
                    mma_bf16(s[2 * jp],     qf[ks], br0);
                    mma_bf16(s[2 * jp + 1], qf[ks], br1);
                }
            }

            float mx_lo = m_lo, mx_hi = m_hi;
#pragma unroll
            for (int j = 0; j < 8; j++) {
                mx_lo = fmaxf(mx_lo, fmaxf(s[j][0], s[j][1]));
                mx_hi = fmaxf(mx_hi, fmaxf(s[j][2], s[j][3]));
            }
            mx_lo = fmaxf(mx_lo, __shfl_xor_sync(0xffffffffu, mx_lo, 1));
            mx_lo = fmaxf(mx_lo, __shfl_xor_sync(0xffffffffu, mx_lo, 2));
            mx_hi = fmaxf(mx_hi, __shfl_xor_sync(0xffffffffu, mx_hi, 1));
            mx_hi = fmaxf(mx_hi, __shfl_xor_sync(0xffffffffu, mx_hi, 2));

            const float c_lo = exp2f(m_lo - mx_lo);
            const float c_hi = exp2f(m_hi - mx_hi);
            float sum_lo = 0.0f, sum_hi = 0.0f;
#pragma unroll
            for (int j = 0; j < 8; j++) {
                s[j][0] = exp2f(s[j][0] - mx_lo);
                s[j][1] = exp2f(s[j][1] - mx_lo);
                s[j][2] = exp2f(s[j][2] - mx_hi);
                s[j][3] = exp2f(s[j][3] - mx_hi);
                sum_lo += s[j][0] + s[j][1];
                sum_hi += s[j][2] + s[j][3];
            }
            sum_lo += __shfl_xor_sync(0xffffffffu, sum_lo, 1);
            sum_lo += __shfl_xor_sync(0xffffffffu, sum_lo, 2);
            sum_hi += __shfl_xor_sync(0xffffffffu, sum_hi, 1);
            sum_hi += __shfl_xor_sync(0xffffffffu, sum_hi, 2);
            l_lo = l_lo * c_lo + sum_lo;
            l_hi = l_hi * c_hi + sum_hi;
            m_lo = mx_lo;
            m_hi = mx_hi;

#pragma unroll
            for (int j = 0; j < 8; j++) {
                o[j][0] *= c_lo; o[j][1] *= c_lo;
                o[j][2] *= c_hi; o[j][3] *= c_hi;
            }

#pragma unroll
            for (int ks = 0; ks < 4; ks++) {
                uint32_t a[4];
                a[0] = pack_bf16(s[2 * ks][0],     s[2 * ks][1]);
                a[1] = pack_bf16(s[2 * ks][2],     s[2 * ks][3]);
                a[2] = pack_bf16(s[2 * ks + 1][0], s[2 * ks + 1][1]);
                a[3] = pack_bf16(s[2 * ks + 1][2], s[2 * ks + 1][3]);
#pragma unroll
                for (int jp = 0; jp < 4; jp++) {
                    uint32_t b0, b1, b2, b3;
                    ldmatrix_x4(b0, b1, b2, b3,
                                v_lm + (uint32_t)(jp * 16 * UKSTRIDE + ks * 8) * 4);
                    uint32_t br0[2] = {b0, b1};
                    uint32_t br1[2] = {b2, b3};
                    mma_bf16(o[2 * jp],     a, br0);
                    mma_bf16(o[2 * jp + 1], a, br1);
                }
            }

            cs = (cs == 2) ? 0 : cs + 1;
            fs = (fs == 2) ? 0 : fs + 1;
        }

        const float inv_lo = 1.0f / l_lo;
        const float inv_hi = 1.0f / l_hi;
        const int n_lo = qt * 128 + wrow + qr;
#pragma unroll
        for (int j = 0; j < 8; j++) {
            const int col = h * 64 + j * 8 + 2 * qc;
            *(float2*)&g_att[((size_t)b * SEQ + n_lo) * INNER + col] =
                make_float2(tf32r(o[j][0] * inv_lo), tf32r(o[j][1] * inv_lo));
            *(float2*)&g_att[((size_t)b * SEQ + n_lo + 8) * INNER + col] =
                make_float2(tf32r(o[j][2] * inv_hi), tf32r(o[j][3] * inv_hi));
        }
    }
}

// ---------------------------------------------------------------------------
// Kernel 3: output projection (r11-proven: BM=128 x BN=128, non-persistent).
// ---------------------------------------------------------------------------
__global__ __launch_bounds__(256, 2) void proj_kernel(const float* __restrict__ bp,
                                                      float* __restrict__ out) {
    extern __shared__ float smf[];
    const uint32_t su = (uint32_t)__cvta_generic_to_shared(smf);
    const float* Wp = g_w + 3 * (size_t)NWF;

    const int bm = blockIdx.y * 128;
    const int bn = blockIdx.x * 128;
    const int t  = threadIdx.x;
    const int warp = t >> 5;
    const int lane = t & 31;
    const int m_base = (warp >> 1) * 32;
    const int n_base = (warp & 1) * 64;
    const int qr = lane >> 2;
    const int qc = lane & 3;

    float acc[2][8][4];
#pragma unroll
    for (int mt = 0; mt < 2; mt++)
#pragma unroll
        for (int j = 0; j < 8; j++)
#pragma unroll
            for (int e = 0; e < 4; e++) acc[mt][j][e] = 0.0f;

    gemm_fill(su, 0, 0, g_att, bm, Wp, bn, t);
    CP_COMMIT();
    gemm_fill(su, 1, 32, g_att, bm, Wp, bn, t);
    CP_COMMIT();

    int cs = 0, fs = 2;
    for (int kt = 0; kt < INNER / 32; kt++) {
        if (kt + 1 < INNER / 32) { CP_WAIT1(); } else { CP_WAIT0(); }
        __syncthreads();
        if (kt + 2 < INNER / 32) {
            gemm_fill(su, fs, (kt + 2) * 32, g_att, bm, Wp, bn, t);
            CP_COMMIT();
        }
        gemm_compute(smf, cs, m_base, n_base, qr, qc, acc);
        cs = (cs == 2) ? 0 : cs + 1;
        fs = (fs == 2) ? 0 : fs + 1;
    }

#pragma unroll
    for (int mt = 0; mt < 2; mt++) {
#pragma unroll
        for (int j = 0; j < 8; j++) {
            const int row0 = bm + m_base + mt * 16 + qr;
            const int col0 = bn + n_base + j * 8 + 2 * qc;
            out[(size_t)row0 * DIM + col0]           = acc[mt][j][0] + bp[col0];
            out[(size_t)row0 * DIM + col0 + 1]       = acc[mt][j][1] + bp[col0 + 1];
            out[(size_t)(row0 + 8) * DIM + col0]     = acc[mt][j][2] + bp[col0];
            out[(size_t)(row0 + 8) * DIM + col0 + 1] = acc[mt][j][3] + bp[col0 + 1];
        }
    }
}

// ---------------------------------------------------------------------------
extern "C" void kernel_launch(void* const* d_in, const int* in_sizes, int n_in,
                              void* d_out, int out_size) {
    const float* x  = (const float*)d_in[0];
    const float* Wq = (const float*)d_in[1];
    const float* Wk = (const float*)d_in[2];
    const float* Wv = (const float*)d_in[3];
    const float* Wp = (const float*)d_in[4];
    const float* bp = (const float*)d_in[5];
    float* out = (float*)d_out;

    int dev = 0, sms = 148;
    cudaGetDevice(&dev);
    cudaDeviceGetAttribute(&sms, cudaDevAttrMultiProcessorCount, dev);
    const int slots = 2 * sms;

    const int gemm_smem  = GEMM_SMEM_FLOATS * (int)sizeof(float);   // 107520
    const int flash_smem = FLASH_SMEM_U * (int)sizeof(uint32_t);    // 73728
    cudaFuncSetAttribute(qkv_kernel,
                         cudaFuncAttributeMaxDynamicSharedMemorySize, gemm_smem);
    cudaFuncSetAttribute(flash_kernel,
                         cudaFuncAttributeMaxDynamicSharedMemorySize, flash_smem);
    cudaFuncSetAttribute(proj_kernel,
                         cudaFuncAttributeMaxDynamicSharedMemorySize, gemm_smem);

    // 0) tf32-round weights only (x consumed raw)
    round_kernel<<<4 * NWF / 1024, 256>>>(Wq, Wk, Wv, Wp);

    // 1) QKV projections (persistent, coalesced epilogue)
    const int g1 = (QKV_UNITS < slots) ? QKV_UNITS : slots;
    qkv_kernel<<<g1, 256, gemm_smem>>>(x);

    // 2) flash attention (persistent)
    const int g2 = (FLASH_UNITS < slots) ? FLASH_UNITS : slots;
    flash_kernel<<<g2, 256, flash_smem>>>();

    // 3) output projection + bias (non-persistent BN=128)
    proj_kernel<<<dim3(DIM / 128, MROWS / 128), 256, gemm_smem>>>(bp, out);
}